// round 12
// baseline (speedup 1.0000x reference)
#include <cuda_runtime.h>
#include <cuda_bf16.h>
#include <stdint.h>

#define CCH 128
#define GTHREADS 512
#define GRIDP 148

// ---- device scratch ----
__device__ float    g_bias[32 * CCH];
__device__ uint32_t g_Wtm[2][CCH][128];        // [hi/lo][o][k/2] bf16x2 of [W0 W1]
__device__ uint32_t g_P0h[524288 * 64], g_P0l[524288 * 64];  // gathered input planes
__device__ uint32_t g_P1h[262144 * 64], g_P1l[262144 * 64];  // even-dst planes
__device__ uint32_t g_P2h[131072 * 64], g_P2l[131072 * 64];  // odd-dst planes
__device__ int      g_barCount;
__device__ volatile unsigned g_barGen;

// ---- SMEM layout (bytes) ----
#define SM_XH   0                   // 129 rows x 256B
#define SM_XL   33024
#define SM_WH   66048               // 128 rows x 512B
#define SM_WL   (66048 + 65536)
#define SM_STAGE 197120             // 2 planes x 32 rows x 272B
#define SM_TOT   214528
#define STG_ROW 272

__device__ __forceinline__ uint32_t smem_u32(const void* p) {
    uint32_t a;
    asm("{ .reg .u64 t; cvta.to.shared.u64 t, %1; cvt.u32.u64 %0, t; }" : "=r"(a) : "l"(p));
    return a;
}
__device__ __forceinline__ void ldx4(uint32_t& r0, uint32_t& r1, uint32_t& r2, uint32_t& r3,
                                     uint32_t addr) {
    asm volatile("ldmatrix.sync.aligned.m8n8.x4.shared.b16 {%0,%1,%2,%3}, [%4];"
                 : "=r"(r0), "=r"(r1), "=r"(r2), "=r"(r3) : "r"(addr));
}
__device__ __forceinline__ void mma_bf16(float* d, const uint32_t* a, const uint32_t* b) {
    asm volatile("mma.sync.aligned.m16n8k16.row.col.f32.bf16.bf16.f32 "
                 "{%0,%1,%2,%3}, {%4,%5,%6,%7}, {%8,%9}, {%0,%1,%2,%3};"
                 : "+f"(d[0]), "+f"(d[1]), "+f"(d[2]), "+f"(d[3])
                 : "r"(a[0]), "r"(a[1]), "r"(a[2]), "r"(a[3]), "r"(b[0]), "r"(b[1]));
}
#define STS64(addr, x, y) \
    asm volatile("st.shared.v2.u32 [%0], {%1,%2};" :: "r"(addr), "r"(x), "r"(y) : "memory")
#define STS32(addr, x) \
    asm volatile("st.shared.u32 [%0], %1;" :: "r"(addr), "r"(x) : "memory")
#define CP_ASYNC16(dst, src) \
    asm volatile("cp.async.cg.shared.global [%0], [%1], 16;" :: "r"(dst), "l"(src) : "memory")
#define CP_COMMIT() asm volatile("cp.async.commit_group;" ::: "memory")
#define CP_WAIT0()  asm volatile("cp.async.wait_group 0;" ::: "memory")

__device__ __forceinline__ void pack_hl(float a, float b, uint32_t& hp, uint32_t& lp) {
    __nv_bfloat16 ha = __float2bfloat16_rn(a), hb = __float2bfloat16_rn(b);
    __nv_bfloat16 la = __float2bfloat16_rn(a - __bfloat162float(ha));
    __nv_bfloat16 lb = __float2bfloat16_rn(b - __bfloat162float(hb));
    __nv_bfloat162 h = {ha, hb}, lo = {la, lb};
    hp = *(uint32_t*)&h; lp = *(uint32_t*)&lo;
}

__device__ __forceinline__ void grid_barrier() {
    __syncthreads();
    if (threadIdx.x == 0) {
        unsigned gen = g_barGen;
        __threadfence();
        if (atomicAdd(&g_barCount, 1) == (int)gridDim.x - 1) {
            g_barCount = 0;
            __threadfence();
            g_barGen = gen + 1;
        } else {
            while (g_barGen == gen) { }
        }
        __threadfence();
    }
    __syncthreads();
}

// ---------------------------------------------------------------------------
__global__ void precompute_kernel(const float* __restrict__ W,
                                  const float* __restrict__ b,
                                  const float* __restrict__ depth,
                                  int nlev) {
    const int tid = threadIdx.x;
    const int gid = blockIdx.x * blockDim.x + tid;
    const int gsize = gridDim.x * blockDim.x;

    for (int i = gid; i < 2 * CCH * 128; i += gsize) {
        int s = i >> 14, o = (i >> 7) & 127, col = i & 127;
        uint32_t out = 0;
        #pragma unroll
        for (int h = 0; h < 2; ++h) {
            int c = 2 * col + h;
            float w = (c < 128) ? W[(size_t)o * 512 + c * 2]
                                : W[(size_t)o * 512 + (c - 128) * 2 + 1];
            __nv_bfloat16 hi = __float2bfloat16_rn(w);
            __nv_bfloat16 v = (s == 0) ? hi
                              : __float2bfloat16_rn(w - __bfloat162float(hi));
            uint16_t bits = *(uint16_t*)&v;
            out |= (uint32_t)bits << (16 * h);
        }
        g_Wtm[s][o][col] = out;
    }

    const int l = tid & 31;
    const int gw = gid >> 5;
    const int nwarps = gsize >> 5;
    for (int p = gw; p < nlev * CCH; p += nwarps) {
        const int lev = p >> 7, o = p & 127;
        float s = 0.f;
        #pragma unroll
        for (int cc = 0; cc < 4; ++cc) {
            int c = l + cc * 32;
            float ws = W[(size_t)o * 512 + (128 + c) * 2 + 0] +
                       W[(size_t)o * 512 + (128 + c) * 2 + 1];
            s += ws * depth[lev * CCH + c];
        }
        #pragma unroll
        for (int d = 16; d > 0; d >>= 1)
            s += __shfl_xor_sync(0xffffffffu, s, d);
        if (l == 0) g_bias[lev * CCH + o] = b[o] + s;
    }
}

// ---------------------------------------------------------------------------
// Gather + bf16 split: P0[row] = split(x[perm[row]]). Pure memory pass.
// ---------------------------------------------------------------------------
__global__ void gather_kernel(const float* __restrict__ x,
                              const int* __restrict__ perm, int N) {
    const int gid = blockIdx.x * blockDim.x + threadIdx.x;
    const int gsize = gridDim.x * blockDim.x;
    for (int i = gid; i < N * 32; i += gsize) {
        int row = i >> 5, c4 = i & 31;
        float4 v = *((const float4*)(x + (size_t)perm[row] * CCH) + c4);
        uint32_t h0, l0, h1, l1;
        pack_hl(v.x, v.y, h0, l0);
        pack_hl(v.z, v.w, h1, l1);
        *(uint2*)(g_P0h + (size_t)row * 64 + c4 * 2) = make_uint2(h0, h1);
        *(uint2*)(g_P0l + (size_t)row * 64 + c4 * 2) = make_uint2(l0, l1);
    }
}

// ---------------------------------------------------------------------------
// Persistent GEMM: all levels; 512 threads, 16 warps (4m x 4n), 128-pos tiles,
// cp.async bf16 planes, single X buffer, grid barrier between levels.
// ---------------------------------------------------------------------------
__global__ __launch_bounds__(GTHREADS)
void gemm_kernel(float* __restrict__ outp, int N) {
    extern __shared__ char smem[];
    const uint32_t sb = smem_u32(smem);
    char* stage = smem + SM_STAGE;
    const int tid = threadIdx.x, l = tid & 31, wid = tid >> 5;
    const int wm = (wid >> 2) * 32, wn = (wid & 3) * 32;
    const int bid = blockIdx.x;

    // ---- W -> smem once ----
    for (int i = tid; i < 2 * 128 * 64; i += GTHREADS) {
        int split = i >> 13, rem = i & 8191, o = rem >> 6, u = rem & 63;
        uint2 v = ((const uint2*)&g_Wtm[split][o][0])[u];
        uint32_t byte = (uint32_t)o * 512 + (((uint32_t)u * 8) ^ (uint32_t)((o & 7) << 4));
        STS64(sb + (split ? SM_WL : SM_WH) + byte, v.x, v.y);
    }

    // ---- fragment address constants ----
    const int arl = ((l >> 3) & 1) * 8 + (l & 7);
    uint32_t aAddr[2][2], aS[2][2];
    #pragma unroll
    for (int mt = 0; mt < 2; ++mt)
        #pragma unroll
        for (int tap = 0; tap < 2; ++tap) {
            int row = wm + mt * 16 + arl + tap;
            aAddr[mt][tap] = (uint32_t)row * 256;
            aS[mt][tap] = (uint32_t)((row & 7) << 4);
        }
    uint32_t bRow[2], bS[2];
    #pragma unroll
    for (int g = 0; g < 2; ++g) {
        int o = wn + g * 16 + ((l >> 4) & 1) * 8 + (l & 7);
        bRow[g] = (uint32_t)o * 512;
        bS[g] = (uint32_t)((o & 7) << 4);
    }
    const uint32_t a_k8b = ((l >> 4) & 1) * 16;
    const uint32_t b_k8b = ((l >> 3) & 1) * 16;
    const int r2 = l >> 2;
    const bool storer = ((r2 & 1) == 0);
    const int o0 = wn + (l & 3) * 2;

    int L = N;
    for (int lvl = 0; L > 1; ++lvl) {
        const int Lout = (L - 1) >> 1;
        const bool final = (Lout == 1);
        const int ntiles = (Lout + 63) >> 6;
        const uint32_t* srcH = (lvl == 0) ? g_P0h : ((lvl & 1) ? g_P1h : g_P2h);
        const uint32_t* srcL = (lvl == 0) ? g_P0l : ((lvl & 1) ? g_P1l : g_P2l);
        uint32_t* dstH = (lvl & 1) ? g_P2h : g_P1h;
        uint32_t* dstL = (lvl & 1) ? g_P2l : g_P1l;

        float bx[4], by[4];
        #pragma unroll
        for (int nt = 0; nt < 4; ++nt) {
            float2 bb = *(const float2*)&g_bias[lvl * CCH + wn + nt * 8 + (l & 3) * 2];
            bx[nt] = bb.x; by[nt] = bb.y;
        }

        // ---- issue cp.async for first tile ----
        if (bid < ntiles) {
            const int pbase = bid << 7;
            for (int i = tid; i < 129 * 16; i += GTHREADS) {
                int row = i >> 4, c = i & 15;
                int rin = pbase + row; if (rin > L - 1) rin = L - 1;
                uint32_t d = (uint32_t)row * 256 + (((uint32_t)c * 16) ^ (uint32_t)((row & 7) << 4));
                CP_ASYNC16(sb + SM_XH + d, srcH + (size_t)rin * 64 + c * 4);
                CP_ASYNC16(sb + SM_XL + d, srcL + (size_t)rin * 64 + c * 4);
            }
        }
        CP_COMMIT();

        for (int tile = bid; tile < ntiles; tile += GRIDP) {
            CP_WAIT0();
            __syncthreads();

            // ---- MMA ----
            float acc[2][4][4];
            #pragma unroll
            for (int mt = 0; mt < 2; ++mt)
                #pragma unroll
                for (int nt = 0; nt < 4; ++nt)
                    #pragma unroll
                    for (int r = 0; r < 4; ++r) acc[mt][nt][r] = 0.f;

            #pragma unroll
            for (int kt = 0; kt < 16; ++kt) {
                const int tap = kt >> 3;
                const uint32_t chA = (uint32_t)(kt & 7) * 32 + a_k8b;
                const uint32_t chB = (uint32_t)kt * 32 + b_k8b;
                uint32_t Bh[4][2], Bl[4][2];
                ldx4(Bh[0][0], Bh[0][1], Bh[1][0], Bh[1][1], sb + SM_WH + bRow[0] + (chB ^ bS[0]));
                ldx4(Bh[2][0], Bh[2][1], Bh[3][0], Bh[3][1], sb + SM_WH + bRow[1] + (chB ^ bS[1]));
                ldx4(Bl[0][0], Bl[0][1], Bl[1][0], Bl[1][1], sb + SM_WL + bRow[0] + (chB ^ bS[0]));
                ldx4(Bl[2][0], Bl[2][1], Bl[3][0], Bl[3][1], sb + SM_WL + bRow[1] + (chB ^ bS[1]));
                #pragma unroll
                for (int mt = 0; mt < 2; ++mt) {
                    const uint32_t aoff = aAddr[mt][tap] + (chA ^ aS[mt][tap]);
                    uint32_t Ah[4], Al[4];
                    ldx4(Ah[0], Ah[1], Ah[2], Ah[3], sb + SM_XH + aoff);
                    ldx4(Al[0], Al[1], Al[2], Al[3], sb + SM_XL + aoff);
                    #pragma unroll
                    for (int nt = 0; nt < 4; ++nt) {
                        mma_bf16(acc[mt][nt], Ah, Bh[nt]);
                        mma_bf16(acc[mt][nt], Al, Bh[nt]);
                        mma_bf16(acc[mt][nt], Ah, Bl[nt]);
                    }
                }
            }
            __syncthreads();   // all X reads done -> buffer reusable

            // ---- issue cp.async for next tile (lands under epilogue) ----
            const int nexttile = tile + GRIDP;
            if (nexttile < ntiles) {
                const int pbase = nexttile << 7;
                for (int i = tid; i < 129 * 16; i += GTHREADS) {
                    int row = i >> 4, c = i & 15;
                    int rin = pbase + row; if (rin > L - 1) rin = L - 1;
                    uint32_t d = (uint32_t)row * 256 + (((uint32_t)c * 16) ^ (uint32_t)((row & 7) << 4));
                    CP_ASYNC16(sb + SM_XH + d, srcH + (size_t)rin * 64 + c * 4);
                    CP_ASYNC16(sb + SM_XL + d, srcL + (size_t)rin * 64 + c * 4);
                }
            }
            CP_COMMIT();

            // ---- epilogue: bias + leaky + pool (in regs) ----
            #pragma unroll
            for (int mt = 0; mt < 2; ++mt)
                #pragma unroll
                for (int nt = 0; nt < 4; ++nt) {
                    float* d = acc[mt][nt];
                    float v0 = d[0] + bx[nt], v1 = d[1] + by[nt];
                    float v2 = d[2] + bx[nt], v3 = d[3] + by[nt];
                    v0 = v0 >= 0.f ? v0 : 0.2f * v0;
                    v1 = v1 >= 0.f ? v1 : 0.2f * v1;
                    v2 = v2 >= 0.f ? v2 : 0.2f * v2;
                    v3 = v3 >= 0.f ? v3 : 0.2f * v3;
                    d[0] = fmaxf(v0, __shfl_xor_sync(0xffffffffu, v0, 4));
                    d[1] = fmaxf(v1, __shfl_xor_sync(0xffffffffu, v1, 4));
                    d[2] = fmaxf(v2, __shfl_xor_sync(0xffffffffu, v2, 4));
                    d[3] = fmaxf(v3, __shfl_xor_sync(0xffffffffu, v3, 4));
                }

            // ---- two stage passes: h=0 -> j 0..31 (wid<8), h=1 -> j 32..63 ----
            const int jbase = tile << 6;
            #pragma unroll
            for (int h = 0; h < 2; ++h) {
                if ((wid >> 3) == h && storer) {
                    #pragma unroll
                    for (int mt = 0; mt < 2; ++mt)
                        #pragma unroll
                        for (int nt = 0; nt < 4; ++nt) {
                            float* d = acc[mt][nt];
                            const int oc = o0 + nt * 8;
                            const int s = ((wm + mt * 16 + r2) >> 1) - h * 32;  // 0..31
                            uint32_t hp, lp;
                            pack_hl(d[0], d[1], hp, lp);
                            STS32(sb + SM_STAGE + s * STG_ROW + oc * 2, hp);
                            STS32(sb + SM_STAGE + 8704 + s * STG_ROW + oc * 2, lp);
                            pack_hl(d[2], d[3], hp, lp);
                            STS32(sb + SM_STAGE + (s + 4) * STG_ROW + oc * 2, hp);
                            STS32(sb + SM_STAGE + 8704 + (s + 4) * STG_ROW + oc * 2, lp);
                            if (final && wm + mt * 16 + r2 == 0) {
                                outp[oc] = d[0];
                                outp[oc + 1] = d[1];
                            }
                        }
                }
                __syncthreads();
                #pragma unroll
                for (int k = 0; k < 2; ++k) {
                    int idx = tid + k * GTHREADS;            // 0..1023
                    int plane = idx >> 9, rem = idx & 511;
                    int row = rem >> 4, c = rem & 15;
                    int j = jbase + h * 32 + row;
                    if (j < Lout) {
                        uint4 v = *(const uint4*)(stage + plane * 8704 + row * STG_ROW + c * 16);
                        uint32_t* dst = (plane ? dstL : dstH) + (size_t)j * 64 + c * 4;
                        *(uint4*)dst = v;
                    }
                }
                __syncthreads();
            }
        }

        grid_barrier();
        L = Lout;
    }
}

// ---------------------------------------------------------------------------
extern "C" void kernel_launch(void* const* d_in, const int* in_sizes, int n_in,
                              void* d_out, int out_size) {
    const float* x     = (const float*)d_in[0];
    const float* depth = (const float*)d_in[1];
    const float* W     = (const float*)d_in[2];
    const float* b     = (const float*)d_in[3];
    const int*   perm  = (const int*)d_in[4];
    float* out = (float*)d_out;

    int N = in_sizes[0] / CCH;
    int nlev = 0;
    { int L = N; while (L > 1) { L = (L - 1) / 2; nlev++; } }

    cudaFuncSetAttribute((const void*)gemm_kernel,
                         cudaFuncAttributeMaxDynamicSharedMemorySize, SM_TOT);

    precompute_kernel<<<GRIDP, 256>>>(W, b, depth, nlev);
    gather_kernel<<<2048, 256>>>(x, perm, N);
    gemm_kernel<<<GRIDP, GTHREADS, SM_TOT>>>(out, N);
}

// round 13
// speedup vs baseline: 1.4803x; 1.4803x over previous
#include <cuda_runtime.h>
#include <cuda_fp16.h>
#include <stdint.h>

#define CCH 128
#define THREADS 256
#define GRIDP 148            // persistent grid: 1 CTA/SM, all co-resident

// ---- device scratch ----
__device__ float    g_bias[32 * CCH];
__device__ uint32_t g_Wtm[CCH][128];        // [o][k/2] fp16x2 of Acat=[W0 W1]
__device__ float    g_bufA[262144 * 128];
__device__ float    g_bufB[131072 * 128];
__device__ int      g_barCount;
__device__ volatile unsigned g_barGen;

// ---- SMEM layout (bytes) ----
// X double buffer: [buf][split hi/lo] 65 rows x 256B = 16640 each
#define XBUF(buf, split) ((buf) * 33280 + (split) * 16640)
#define SM_WH  66560                 // W: 128 rows x 512B (fp16, single plane)
#define SM_STAGE 132096              // 32 rows x 136 floats = 17408 B
#define SM_TOT  149504
#define STAGE_STRIDE 136

__device__ __forceinline__ uint32_t smem_u32(const void* p) {
    uint32_t a;
    asm("{ .reg .u64 t; cvta.to.shared.u64 t, %1; cvt.u32.u64 %0, t; }" : "=r"(a) : "l"(p));
    return a;
}
__device__ __forceinline__ void ldx4(uint32_t& r0, uint32_t& r1, uint32_t& r2, uint32_t& r3,
                                     uint32_t addr) {
    asm volatile("ldmatrix.sync.aligned.m8n8.x4.shared.b16 {%0,%1,%2,%3}, [%4];"
                 : "=r"(r0), "=r"(r1), "=r"(r2), "=r"(r3) : "r"(addr));
}
__device__ __forceinline__ void mma_f16(float* d, const uint32_t* a, const uint32_t* b) {
    asm volatile("mma.sync.aligned.m16n8k16.row.col.f32.f16.f16.f32 "
                 "{%0,%1,%2,%3}, {%4,%5,%6,%7}, {%8,%9}, {%0,%1,%2,%3};"
                 : "+f"(d[0]), "+f"(d[1]), "+f"(d[2]), "+f"(d[3])
                 : "r"(a[0]), "r"(a[1]), "r"(a[2]), "r"(a[3]), "r"(b[0]), "r"(b[1]));
}
#define STS64(addr, x, y) \
    asm volatile("st.shared.v2.u32 [%0], {%1,%2};" :: "r"(addr), "r"(x), "r"(y) : "memory")

// split float4 into fp16 hi plane + fp16 residual plane (x = hi + lo to ~2^-23)
__device__ __forceinline__ void cvt_sts(float4 v, uint32_t dstH, uint32_t dstL) {
    __half h0 = __float2half_rn(v.x), h1 = __float2half_rn(v.y);
    __half h2 = __float2half_rn(v.z), h3 = __float2half_rn(v.w);
    __half l0 = __float2half_rn(v.x - __half2float(h0));
    __half l1 = __float2half_rn(v.y - __half2float(h1));
    __half l2 = __float2half_rn(v.z - __half2float(h2));
    __half l3 = __float2half_rn(v.w - __half2float(h3));
    __half2 hp0 = {h0, h1}, hp1 = {h2, h3}, lp0 = {l0, l1}, lp1 = {l2, l3};
    STS64(dstH, *(uint32_t*)&hp0, *(uint32_t*)&hp1);
    STS64(dstL, *(uint32_t*)&lp0, *(uint32_t*)&lp1);
}

// sense-reversing grid barrier; safe: all GRIDP CTAs co-resident (1 CTA/SM).
__device__ __forceinline__ void grid_barrier() {
    __syncthreads();
    if (threadIdx.x == 0) {
        unsigned gen = g_barGen;
        __threadfence();
        if (atomicAdd(&g_barCount, 1) == (int)gridDim.x - 1) {
            g_barCount = 0;
            __threadfence();
            g_barGen = gen + 1;
        } else {
            while (g_barGen == gen) { }
        }
        __threadfence();
    }
    __syncthreads();
}

// ---------------------------------------------------------------------------
// Parallel precompute: W -> fp16 plane; per-level bias via warp dot products.
// ---------------------------------------------------------------------------
__global__ void precompute_kernel(const float* __restrict__ W,
                                  const float* __restrict__ b,
                                  const float* __restrict__ depth,
                                  int nlev) {
    const int tid = threadIdx.x;
    const int gid = blockIdx.x * blockDim.x + tid;
    const int gsize = gridDim.x * blockDim.x;

    for (int i = gid; i < CCH * 128; i += gsize) {
        int o = (i >> 7) & 127, col = i & 127;
        uint32_t out = 0;
        #pragma unroll
        for (int h = 0; h < 2; ++h) {
            int c = 2 * col + h;
            float w = (c < 128) ? W[(size_t)o * 512 + c * 2]
                                : W[(size_t)o * 512 + (c - 128) * 2 + 1];
            __half hv = __float2half_rn(w);
            uint16_t bits = *(uint16_t*)&hv;
            out |= (uint32_t)bits << (16 * h);
        }
        g_Wtm[o][col] = out;
    }

    const int l = tid & 31;
    const int gw = gid >> 5;
    const int nwarps = gsize >> 5;
    for (int p = gw; p < nlev * CCH; p += nwarps) {
        const int lev = p >> 7, o = p & 127;
        float s = 0.f;
        #pragma unroll
        for (int cc = 0; cc < 4; ++cc) {
            int c = l + cc * 32;
            float ws = W[(size_t)o * 512 + (128 + c) * 2 + 0] +
                       W[(size_t)o * 512 + (128 + c) * 2 + 1];
            s += ws * depth[lev * CCH + c];
        }
        #pragma unroll
        for (int d = 16; d > 0; d >>= 1)
            s += __shfl_xor_sync(0xffffffffu, s, d);
        if (l == 0) g_bias[lev * CCH + o] = b[o] + s;
    }
}

// ---------------------------------------------------------------------------
// Persistent: all levels, one launch; grid barrier between levels.
// fp16 split-2: D = (Xh + Xl) * Wh, 2 MMA products, fp32 accum.
// ---------------------------------------------------------------------------
__global__ __launch_bounds__(THREADS)
void persistent_kernel(const float* __restrict__ Xin, const int* __restrict__ perm,
                       float* bufA, float* bufB, float* outp, int N) {
    extern __shared__ char smem[];
    const uint32_t sb = smem_u32(smem);
    float* stagef = (float*)(smem + SM_STAGE);
    const int tid = threadIdx.x, l = tid & 31, wid = tid >> 5;
    const int wm = (wid >> 2) * 32, wn = (wid & 3) * 32;
    const int bid = blockIdx.x;

    // ---- W -> smem once for the whole run ----
    for (int i = tid; i < 128 * 64; i += THREADS) {
        int o = i >> 6, u = i & 63;
        uint2 v = ((const uint2*)&g_Wtm[o][0])[u];
        uint32_t byte = (uint32_t)o * 512 + (((uint32_t)u * 8) ^ (uint32_t)((o & 7) << 4));
        STS64(sb + SM_WH + byte, v.x, v.y);
    }

    // ---- per-lane fragment address constants ----
    const int arl = ((l >> 3) & 1) * 8 + (l & 7);
    uint32_t aAddr[2][2], aS[2][2];
    #pragma unroll
    for (int mt = 0; mt < 2; ++mt)
        #pragma unroll
        for (int tap = 0; tap < 2; ++tap) {
            int row = wm + mt * 16 + arl + tap;
            aAddr[mt][tap] = (uint32_t)row * 256;
            aS[mt][tap] = (uint32_t)((row & 7) << 4);
        }
    uint32_t bRow[2], bS[2];
    #pragma unroll
    for (int g = 0; g < 2; ++g) {
        int o = wn + g * 16 + ((l >> 4) & 1) * 8 + (l & 7);
        bRow[g] = (uint32_t)o * 512;
        bS[g] = (uint32_t)((o & 7) << 4);
    }
    const uint32_t a_k8b = ((l >> 4) & 1) * 16;
    const uint32_t b_k8b = ((l >> 3) & 1) * 16;
    const uint32_t xswz = ((uint32_t)l * 8) ^ ((uint32_t)wid << 4);

    const float* Xcur = Xin;
    int L = N;

    for (int lvl = 0; L > 1; ++lvl) {
        const int Lout = (L - 1) >> 1;
        float* Yout = (Lout == 1) ? outp : ((lvl & 1) ? bufB : bufA);
        const int* pm = (lvl == 0) ? perm : nullptr;
        const int ntiles = (Lout + 31) >> 5;

        float bx[4], by[4];
        #pragma unroll
        for (int nt = 0; nt < 4; ++nt) {
            float2 bb = *(const float2*)&g_bias[lvl * CCH + wn + nt * 8 + (l & 3) * 2];
            bx[nt] = bb.x; by[nt] = bb.y;
        }

        // ---- prologue: load first tile into buf 0 ----
        int cur = 0;
        if (bid < ntiles) {
            const int pbase = bid << 6;
            #pragma unroll
            for (int s9 = 0; s9 < 9; ++s9) {
                if (s9 == 8 && wid != 0) break;
                int row = s9 * 8 + wid;
                int pin = pbase + row; if (pin > L - 1) pin = L - 1;
                size_t srow = pm ? (size_t)pm[pin] : (size_t)pin;
                float4 v = *((const float4*)(Xcur + srow * CCH) + l);
                uint32_t byte = (uint32_t)row * 256 + xswz;
                cvt_sts(v, sb + XBUF(0, 0) + byte, sb + XBUF(0, 1) + byte);
            }
        }
        __syncthreads();

        for (int tile = bid; tile < ntiles; tile += GRIDP) {
            const int nexttile = tile + GRIDP;
            const bool hasnext = nexttile < ntiles;

            // ---- 1. prefetch next tile's X into registers ----
            float4 pr[9];
            if (hasnext) {
                const int pbase = nexttile << 6;
                #pragma unroll
                for (int s9 = 0; s9 < 9; ++s9) {
                    if (s9 == 8 && wid != 0) break;
                    int row = s9 * 8 + wid;
                    int pin = pbase + row; if (pin > L - 1) pin = L - 1;
                    size_t srow = pm ? (size_t)pm[pin] : (size_t)pin;
                    pr[s9] = *((const float4*)(Xcur + srow * CCH) + l);
                }
            }

            // ---- 2. MMA from buf[cur]: 2 fp16 products ----
            float acc[2][4][4];
            #pragma unroll
            for (int mt = 0; mt < 2; ++mt)
                #pragma unroll
                for (int nt = 0; nt < 4; ++nt)
                    #pragma unroll
                    for (int r = 0; r < 4; ++r) acc[mt][nt][r] = 0.f;

            const uint32_t xbH = sb + XBUF(cur, 0);
            const uint32_t xbL = sb + XBUF(cur, 1);
            #pragma unroll
            for (int kt = 0; kt < 16; ++kt) {
                const int tap = kt >> 3;
                const uint32_t chA = (uint32_t)(kt & 7) * 32 + a_k8b;
                const uint32_t chB = (uint32_t)kt * 32 + b_k8b;

                uint32_t Bh[4][2];
                ldx4(Bh[0][0], Bh[0][1], Bh[1][0], Bh[1][1], sb + SM_WH + bRow[0] + (chB ^ bS[0]));
                ldx4(Bh[2][0], Bh[2][1], Bh[3][0], Bh[3][1], sb + SM_WH + bRow[1] + (chB ^ bS[1]));

                #pragma unroll
                for (int mt = 0; mt < 2; ++mt) {
                    const uint32_t aoff = aAddr[mt][tap] + (chA ^ aS[mt][tap]);
                    uint32_t Ah[4], Al[4];
                    ldx4(Ah[0], Ah[1], Ah[2], Ah[3], xbH + aoff);
                    ldx4(Al[0], Al[1], Al[2], Al[3], xbL + aoff);
                    #pragma unroll
                    for (int nt = 0; nt < 4; ++nt) {
                        mma_f16(acc[mt][nt], Ah, Bh[nt]);
                        mma_f16(acc[mt][nt], Al, Bh[nt]);
                    }
                }
            }

            // ---- 3. cvt + STS prefetched tile into buf[cur^1] ----
            if (hasnext) {
                const uint32_t dH = sb + XBUF(cur ^ 1, 0);
                const uint32_t dL = sb + XBUF(cur ^ 1, 1);
                #pragma unroll
                for (int s9 = 0; s9 < 9; ++s9) {
                    if (s9 == 8 && wid != 0) break;
                    uint32_t byte = (uint32_t)(s9 * 8 + wid) * 256 + xswz;
                    cvt_sts(pr[s9], dH + byte, dL + byte);
                }
            }

            // ---- 4. epilogue: bias + leaky + pool(2) -> stage ----
            const int r2 = l >> 2;
            const bool storer = ((r2 & 1) == 0);
            #pragma unroll
            for (int mt = 0; mt < 2; ++mt)
                #pragma unroll
                for (int nt = 0; nt < 4; ++nt) {
                    float* d = acc[mt][nt];
                    float v0 = d[0] + bx[nt], v1 = d[1] + by[nt];
                    float v2 = d[2] + bx[nt], v3 = d[3] + by[nt];
                    v0 = v0 >= 0.f ? v0 : 0.2f * v0;
                    v1 = v1 >= 0.f ? v1 : 0.2f * v1;
                    v2 = v2 >= 0.f ? v2 : 0.2f * v2;
                    v3 = v3 >= 0.f ? v3 : 0.2f * v3;
                    float u0 = fmaxf(v0, __shfl_xor_sync(0xffffffffu, v0, 4));
                    float u1 = fmaxf(v1, __shfl_xor_sync(0xffffffffu, v1, 4));
                    float u2 = fmaxf(v2, __shfl_xor_sync(0xffffffffu, v2, 4));
                    float u3 = fmaxf(v3, __shfl_xor_sync(0xffffffffu, v3, 4));
                    if (storer) {
                        const int o0 = wn + nt * 8 + (l & 3) * 2;
                        const int jl = (wm + mt * 16 + r2) >> 1;   // 0..31
                        *(float2*)&stagef[jl * STAGE_STRIDE + o0] = make_float2(u0, u1);
                        *(float2*)&stagef[(jl + 4) * STAGE_STRIDE + o0] = make_float2(u2, u3);
                    }
                }
            __syncthreads();   // STS (buf^1) + stage complete

            // ---- 5. coalesced store: 32 rows x 128 floats ----
            const int jbase = tile << 5;
            #pragma unroll
            for (int k = 0; k < 4; ++k) {
                int idx = tid + k * THREADS;
                int row = idx >> 5, c4 = idx & 31;
                if (jbase + row < Lout) {
                    float4 v = *(const float4*)&stagef[row * STAGE_STRIDE + c4 * 4];
                    *(float4*)&Yout[(size_t)(jbase + row) * CCH + c4 * 4] = v;
                }
            }
            __syncthreads();   // stage free before next epilogue
            cur ^= 1;
        }

        grid_barrier();        // level complete chip-wide
        Xcur = Yout;
        L = Lout;
    }
}

// ---------------------------------------------------------------------------
extern "C" void kernel_launch(void* const* d_in, const int* in_sizes, int n_in,
                              void* d_out, int out_size) {
    const float* x     = (const float*)d_in[0];
    const float* depth = (const float*)d_in[1];
    const float* W     = (const float*)d_in[2];
    const float* b     = (const float*)d_in[3];
    const int*   perm  = (const int*)d_in[4];
    float* out = (float*)d_out;

    int N = in_sizes[0] / CCH;
    int nlev = 0;
    { int L = N; while (L > 1) { L = (L - 1) / 2; nlev++; } }

    cudaFuncSetAttribute((const void*)persistent_kernel,
                         cudaFuncAttributeMaxDynamicSharedMemorySize, SM_TOT);

    precompute_kernel<<<GRIDP, 256>>>(W, b, depth, nlev);

    float *bufA, *bufB;
    cudaGetSymbolAddress((void**)&bufA, g_bufA);
    cudaGetSymbolAddress((void**)&bufB, g_bufB);

    persistent_kernel<<<GRIDP, THREADS, SM_TOT>>>(x, perm, bufA, bufB, out, N);
}